// round 9
// baseline (speedup 1.0000x reference)
#include <cuda_runtime.h>
#include <cuda_bf16.h>

#define NN 100000
#define EE 1600000

// Scratch (device globals: allocation-free rule).
__device__ float g_bufA[NN * 64];
__device__ float g_bufB[NN * 64];
__device__ int   g_offs[NN + 1];      // CSR row offsets (by dst)
__device__ int   g_cursor[NN];        // scatter cursors
__device__ uint2 g_perm[EE];          // {src, weight_bits} sorted by dst

// ---------------------------------------------------------------------------
// CSR build
// ---------------------------------------------------------------------------
__global__ void k_zero_offs(int n1) {
    int i = blockIdx.x * blockDim.x + threadIdx.x;
    if (i < n1) g_offs[i] = 0;
}

__global__ void k_hist(const int* __restrict__ dst, int e) {
    int i = blockIdx.x * blockDim.x + threadIdx.x;
    if (i < e) atomicAdd(&g_offs[dst[i] + 1], 1);
}

// Single-block inclusive prefix scan over g_offs[0..len). Also seeds cursors.
__global__ void k_scan(int len, int nnodes) {
    __shared__ int s[1024];
    int t = threadIdx.x;
    int chunk = (len + 1023) / 1024;
    int b0 = t * chunk;
    int b1 = min(b0 + chunk, len);
    int sum = 0;
    for (int i = b0; i < b1; i++) sum += g_offs[i];
    s[t] = sum;
    __syncthreads();
    for (int off = 1; off < 1024; off <<= 1) {
        int v = (t >= off) ? s[t - off] : 0;
        __syncthreads();
        s[t] += v;
        __syncthreads();
    }
    int run = s[t] - sum;   // exclusive base for this chunk
    for (int i = b0; i < b1; i++) {
        run += g_offs[i];
        g_offs[i] = run;
        if (i < nnodes) g_cursor[i] = run;
    }
}

__global__ void k_scatter(const int* __restrict__ src, const int* __restrict__ dst,
                          const float* __restrict__ w, int e) {
    int i = blockIdx.x * blockDim.x + threadIdx.x;
    if (i < e) {
        int p = atomicAdd(&g_cursor[dst[i]], 1);
        g_perm[p] = make_uint2((unsigned)src[i], __float_as_uint(w[i]));
    }
}

// ---------------------------------------------------------------------------
// Fused GCN layer: Hout[n] = act( (sum_e w_e * Hin[src_e]) @ W + b )
// One warp per node, grid-stride. Aggregated row lives across the warp
// (float2/lane = 64 ch). Mini-GEMM via warp shuffles + W in smem.
// Unroll-8 gather (MLP=8); 2-way split accumulators in the GEMM.
// ---------------------------------------------------------------------------
#define LAYER_BLOCKS 888   // 148 SMs * 6 blocks

__device__ __forceinline__ void layer_body(const float2* __restrict__ Hin,
                                           float* __restrict__ Hout,
                                           const float* __restrict__ Wg,
                                           const float* __restrict__ bg,
                                           int n, int outc, int relu) {
    __shared__ float Ws[64 * 64];
    __shared__ float bs[64];
    int tid = threadIdx.x;
    for (int i = tid; i < 64 * 64; i += 256) Ws[i] = 0.f;
    __syncthreads();
    for (int i = tid; i < 64 * outc; i += 256) {
        int k = i / outc, c = i % outc;
        Ws[k * 64 + c] = Wg[i];
    }
    if (tid < 64) bs[tid] = (tid < outc) ? bg[tid] : 0.f;
    __syncthreads();

    int warp = tid >> 5;
    int lane = tid & 31;
    int c0 = lane * 2;

    for (int node = blockIdx.x * 8 + warp; node < n; node += gridDim.x * 8) {
        int beg = g_offs[node];
        int end = g_offs[node + 1];
        float2 acc0 = make_float2(0.f, 0.f);
        float2 acc1 = make_float2(0.f, 0.f);
        int e = beg;
        // unroll-8: all perm loads then all gathers (MLP=8 per warp)
        for (; e + 8 <= end; e += 8) {
            uint2 p0 = g_perm[e + 0];
            uint2 p1 = g_perm[e + 1];
            uint2 p2 = g_perm[e + 2];
            uint2 p3 = g_perm[e + 3];
            uint2 p4 = g_perm[e + 4];
            uint2 p5 = g_perm[e + 5];
            uint2 p6 = g_perm[e + 6];
            uint2 p7 = g_perm[e + 7];
            float2 v0 = Hin[p0.x * 32u + lane];
            float2 v1 = Hin[p1.x * 32u + lane];
            float2 v2 = Hin[p2.x * 32u + lane];
            float2 v3 = Hin[p3.x * 32u + lane];
            float2 v4 = Hin[p4.x * 32u + lane];
            float2 v5 = Hin[p5.x * 32u + lane];
            float2 v6 = Hin[p6.x * 32u + lane];
            float2 v7 = Hin[p7.x * 32u + lane];
            float w0 = __uint_as_float(p0.y);
            float w1 = __uint_as_float(p1.y);
            float w2 = __uint_as_float(p2.y);
            float w3 = __uint_as_float(p3.y);
            float w4 = __uint_as_float(p4.y);
            float w5 = __uint_as_float(p5.y);
            float w6 = __uint_as_float(p6.y);
            float w7 = __uint_as_float(p7.y);
            acc0.x = fmaf(w0, v0.x, acc0.x); acc0.y = fmaf(w0, v0.y, acc0.y);
            acc1.x = fmaf(w1, v1.x, acc1.x); acc1.y = fmaf(w1, v1.y, acc1.y);
            acc0.x = fmaf(w2, v2.x, acc0.x); acc0.y = fmaf(w2, v2.y, acc0.y);
            acc1.x = fmaf(w3, v3.x, acc1.x); acc1.y = fmaf(w3, v3.y, acc1.y);
            acc0.x = fmaf(w4, v4.x, acc0.x); acc0.y = fmaf(w4, v4.y, acc0.y);
            acc1.x = fmaf(w5, v5.x, acc1.x); acc1.y = fmaf(w5, v5.y, acc1.y);
            acc0.x = fmaf(w6, v6.x, acc0.x); acc0.y = fmaf(w6, v6.y, acc0.y);
            acc1.x = fmaf(w7, v7.x, acc1.x); acc1.y = fmaf(w7, v7.y, acc1.y);
        }
        for (; e + 4 <= end; e += 4) {
            uint2 p0 = g_perm[e + 0];
            uint2 p1 = g_perm[e + 1];
            uint2 p2 = g_perm[e + 2];
            uint2 p3 = g_perm[e + 3];
            float2 v0 = Hin[p0.x * 32u + lane];
            float2 v1 = Hin[p1.x * 32u + lane];
            float2 v2 = Hin[p2.x * 32u + lane];
            float2 v3 = Hin[p3.x * 32u + lane];
            float w0 = __uint_as_float(p0.y);
            float w1 = __uint_as_float(p1.y);
            float w2 = __uint_as_float(p2.y);
            float w3 = __uint_as_float(p3.y);
            acc0.x = fmaf(w0, v0.x, acc0.x); acc0.y = fmaf(w0, v0.y, acc0.y);
            acc1.x = fmaf(w1, v1.x, acc1.x); acc1.y = fmaf(w1, v1.y, acc1.y);
            acc0.x = fmaf(w2, v2.x, acc0.x); acc0.y = fmaf(w2, v2.y, acc0.y);
            acc1.x = fmaf(w3, v3.x, acc1.x); acc1.y = fmaf(w3, v3.y, acc1.y);
        }
        for (; e < end; ++e) {
            uint2 p = g_perm[e];
            float2 v = Hin[p.x * 32u + lane];
            float w = __uint_as_float(p.y);
            acc0.x = fmaf(w, v.x, acc0.x);
            acc0.y = fmaf(w, v.y, acc0.y);
        }
        float2 acc = make_float2(acc0.x + acc1.x, acc0.y + acc1.y);

        // mini-GEMM: out[c0,c0+1] = sum_k row[k] * Ws[k][c0..c0+1] + b
        // 2 independent accumulation chains (halve the serial FFMA depth).
        float ox0 = 0.f, oy0 = 0.f, ox1 = 0.f, oy1 = 0.f;
#pragma unroll
        for (int k2 = 0; k2 < 32; k2 += 2) {
            float rxa = __shfl_sync(0xffffffffu, acc.x, k2);
            float rya = __shfl_sync(0xffffffffu, acc.y, k2);
            float rxb = __shfl_sync(0xffffffffu, acc.x, k2 + 1);
            float ryb = __shfl_sync(0xffffffffu, acc.y, k2 + 1);
            float2 wa0 = *(const float2*)&Ws[(2 * k2) * 64 + c0];
            float2 wa1 = *(const float2*)&Ws[(2 * k2 + 1) * 64 + c0];
            float2 wb0 = *(const float2*)&Ws[(2 * k2 + 2) * 64 + c0];
            float2 wb1 = *(const float2*)&Ws[(2 * k2 + 3) * 64 + c0];
            ox0 = fmaf(rxa, wa0.x, ox0); oy0 = fmaf(rxa, wa0.y, oy0);
            ox0 = fmaf(rya, wa1.x, ox0); oy0 = fmaf(rya, wa1.y, oy0);
            ox1 = fmaf(rxb, wb0.x, ox1); oy1 = fmaf(rxb, wb0.y, oy1);
            ox1 = fmaf(ryb, wb1.x, ox1); oy1 = fmaf(ryb, wb1.y, oy1);
        }
        float ox = ox0 + ox1 + bs[c0];
        float oy = oy0 + oy1 + bs[c0 + 1];
        if (relu) { ox = fmaxf(ox, 0.f); oy = fmaxf(oy, 0.f); }

        if (outc == 64) {
            ((float2*)Hout)[node * 32 + lane] = make_float2(ox, oy);
        } else {
            if (c0 + 1 < outc)
                *(float2*)(Hout + (size_t)node * outc + c0) = make_float2(ox, oy);
            else if (c0 < outc)
                Hout[(size_t)node * outc + c0] = ox;
        }
    }
}

// Variants (device globals referenced directly; no cudaGetSymbolAddress)
__global__ void __launch_bounds__(256, 6)
k_layer0(const float2* __restrict__ x, const float* __restrict__ Wg,
         const float* __restrict__ bg, int n) {
    layer_body(x, g_bufA, Wg, bg, n, 64, 1);
}
__global__ void __launch_bounds__(256, 6)
k_layer_AB(const float* __restrict__ Wg, const float* __restrict__ bg, int n) {
    layer_body((const float2*)g_bufA, g_bufB, Wg, bg, n, 64, 1);
}
__global__ void __launch_bounds__(256, 6)
k_layer_BA(const float* __restrict__ Wg, const float* __restrict__ bg, int n) {
    layer_body((const float2*)g_bufB, g_bufA, Wg, bg, n, 64, 1);
}
__global__ void __launch_bounds__(256, 6)
k_layer_Bout(const float* __restrict__ Wg, const float* __restrict__ bg,
             float* __restrict__ out, int n, int outc) {
    layer_body((const float2*)g_bufB, out, Wg, bg, n, outc, 0);
}

// ---------------------------------------------------------------------------
// Launch
// inputs: x[N,64], edge_weight[E], W[4,64,64], b[4,64], W_out[64,40],
//         b_out[40], edge_src[E], edge_dst[E]  -> out[N,40] f32
// ---------------------------------------------------------------------------
extern "C" void kernel_launch(void* const* d_in, const int* in_sizes, int n_in,
                              void* d_out, int out_size) {
    const float* x    = (const float*)d_in[0];
    const float* ew   = (const float*)d_in[1];
    const float* W    = (const float*)d_in[2];
    const float* b    = (const float*)d_in[3];
    const float* Wout = (const float*)d_in[4];
    const float* bout = (const float*)d_in[5];
    const int*   esrc = (const int*)d_in[6];
    const int*   edst = (const int*)d_in[7];

    int n = in_sizes[0] / 64;   // 100000
    int e = in_sizes[6];        // 1600000

    // --- CSR build (dst-sorted) ---
    k_zero_offs<<<(n + 256) / 256, 256>>>(n + 1);
    k_hist<<<(e + 255) / 256, 256>>>(edst, e);
    k_scan<<<1, 1024>>>(n + 1, n);
    k_scatter<<<(e + 255) / 256, 256>>>(esrc, edst, ew, e);

    // --- 5 fused layers (ping-pong A/B) ---
    k_layer0   <<<LAYER_BLOCKS, 256>>>((const float2*)x, W, b, n);
    k_layer_AB <<<LAYER_BLOCKS, 256>>>(W + 1 * 64 * 64, b + 1 * 64, n);
    k_layer_BA <<<LAYER_BLOCKS, 256>>>(W + 2 * 64 * 64, b + 2 * 64, n);
    k_layer_AB <<<LAYER_BLOCKS, 256>>>(W + 3 * 64 * 64, b + 3 * 64, n);
    k_layer_Bout<<<LAYER_BLOCKS, 256>>>(Wout, bout, (float*)d_out, n, 40);
}

// round 13
// speedup vs baseline: 1.2746x; 1.2746x over previous
#include <cuda_runtime.h>
#include <cuda_bf16.h>

#define NN 100000
#define EE 1600000

// Scratch (device globals: allocation-free rule).
__device__ float g_bufA[NN * 64];
__device__ float g_bufB[NN * 64];
__device__ int   g_offs[NN + 1];      // CSR row offsets (by dst)
__device__ int   g_cursor[NN];        // scatter cursors
__device__ uint2 g_perm[EE];          // {src, weight_bits} sorted by dst

// ---------------------------------------------------------------------------
// CSR build
// ---------------------------------------------------------------------------
__global__ void k_zero_offs(int n1) {
    int i = blockIdx.x * blockDim.x + threadIdx.x;
    if (i < n1) g_offs[i] = 0;
}

__global__ void k_hist(const int* __restrict__ dst, int e) {
    int i = blockIdx.x * blockDim.x + threadIdx.x;
    if (i < e) atomicAdd(&g_offs[dst[i] + 1], 1);
}

// Single-block inclusive prefix scan over g_offs[0..len). Also seeds cursors.
__global__ void k_scan(int len, int nnodes) {
    __shared__ int s[1024];
    int t = threadIdx.x;
    int chunk = (len + 1023) / 1024;
    int b0 = t * chunk;
    int b1 = min(b0 + chunk, len);
    int sum = 0;
    for (int i = b0; i < b1; i++) sum += g_offs[i];
    s[t] = sum;
    __syncthreads();
    for (int off = 1; off < 1024; off <<= 1) {
        int v = (t >= off) ? s[t - off] : 0;
        __syncthreads();
        s[t] += v;
        __syncthreads();
    }
    int run = s[t] - sum;   // exclusive base for this chunk
    for (int i = b0; i < b1; i++) {
        run += g_offs[i];
        g_offs[i] = run;
        if (i < nnodes) g_cursor[i] = run;
    }
}

__global__ void k_scatter(const int* __restrict__ src, const int* __restrict__ dst,
                          const float* __restrict__ w, int e) {
    int i = blockIdx.x * blockDim.x + threadIdx.x;
    if (i < e) {
        int p = atomicAdd(&g_cursor[dst[i]], 1);
        g_perm[p] = make_uint2((unsigned)src[i], __float_as_uint(w[i]));
    }
}

// ---------------------------------------------------------------------------
// Fused GCN layer: Hout[n] = act( (sum_e w_e * Hin[src_e]) @ W + b )
// One warp handles 4 NODES per pass: aggregate 4 rows, then one shared
// mini-GEMM pass reusing each W value 4x (W smem traffic per node /4 —
// the MIO pipe (LDS+SHFL) was the measured bottleneck).
// ---------------------------------------------------------------------------
#define LAYER_BLOCKS 740   // 148 SMs * 5 blocks

__device__ __forceinline__ void gather_node(const float2* __restrict__ Hin,
                                            int node, int lane, float2& accOut) {
    int beg = g_offs[node];
    int end = g_offs[node + 1];
    float2 acc = make_float2(0.f, 0.f);
    int e = beg;
    for (; e + 4 <= end; e += 4) {
        uint2 p0 = g_perm[e + 0];
        uint2 p1 = g_perm[e + 1];
        uint2 p2 = g_perm[e + 2];
        uint2 p3 = g_perm[e + 3];
        float2 v0 = Hin[p0.x * 32u + lane];
        float2 v1 = Hin[p1.x * 32u + lane];
        float2 v2 = Hin[p2.x * 32u + lane];
        float2 v3 = Hin[p3.x * 32u + lane];
        float w0 = __uint_as_float(p0.y);
        float w1 = __uint_as_float(p1.y);
        float w2 = __uint_as_float(p2.y);
        float w3 = __uint_as_float(p3.y);
        acc.x = fmaf(w0, v0.x, acc.x); acc.y = fmaf(w0, v0.y, acc.y);
        acc.x = fmaf(w1, v1.x, acc.x); acc.y = fmaf(w1, v1.y, acc.y);
        acc.x = fmaf(w2, v2.x, acc.x); acc.y = fmaf(w2, v2.y, acc.y);
        acc.x = fmaf(w3, v3.x, acc.x); acc.y = fmaf(w3, v3.y, acc.y);
    }
    for (; e < end; ++e) {
        uint2 p = g_perm[e];
        float2 v = Hin[p.x * 32u + lane];
        float w = __uint_as_float(p.y);
        acc.x = fmaf(w, v.x, acc.x);
        acc.y = fmaf(w, v.y, acc.y);
    }
    accOut = acc;
}

__device__ __forceinline__ void layer_body(const float2* __restrict__ Hin,
                                           float* __restrict__ Hout,
                                           const float* __restrict__ Wg,
                                           const float* __restrict__ bg,
                                           int n, int outc, int relu) {
    __shared__ float Ws[64 * 64];
    __shared__ float bs[64];
    int tid = threadIdx.x;
    for (int i = tid; i < 64 * 64; i += 256) Ws[i] = 0.f;
    __syncthreads();
    for (int i = tid; i < 64 * outc; i += 256) {
        int k = i / outc, c = i % outc;
        Ws[k * 64 + c] = Wg[i];
    }
    if (tid < 64) bs[tid] = (tid < outc) ? bg[tid] : 0.f;
    __syncthreads();

    int warp = tid >> 5;
    int lane = tid & 31;
    int c0 = lane * 2;
    int groups = (n + 3) >> 2;

    for (int g = blockIdx.x * 8 + warp; g < groups; g += gridDim.x * 8) {
        int n0 = g * 4;
        float2 acc[4];
#pragma unroll
        for (int j = 0; j < 4; j++) {
            if (n0 + j < n) gather_node(Hin, n0 + j, lane, acc[j]);
            else            acc[j] = make_float2(0.f, 0.f);
        }

        // Batched mini-GEMM: 4 nodes share each W load (W traffic /4).
        float ox[4], oy[4];
#pragma unroll
        for (int j = 0; j < 4; j++) { ox[j] = 0.f; oy[j] = 0.f; }
#pragma unroll
        for (int k2 = 0; k2 < 32; k2++) {
            float2 w0 = *(const float2*)&Ws[(2 * k2) * 64 + c0];
            float2 w1 = *(const float2*)&Ws[(2 * k2 + 1) * 64 + c0];
#pragma unroll
            for (int j = 0; j < 4; j++) {
                float rx = __shfl_sync(0xffffffffu, acc[j].x, k2);
                float ry = __shfl_sync(0xffffffffu, acc[j].y, k2);
                ox[j] = fmaf(rx, w0.x, ox[j]); oy[j] = fmaf(rx, w0.y, oy[j]);
                ox[j] = fmaf(ry, w1.x, ox[j]); oy[j] = fmaf(ry, w1.y, oy[j]);
            }
        }

        float bx = bs[c0];
        float by = bs[c0 + 1];
#pragma unroll
        for (int j = 0; j < 4; j++) {
            int node = n0 + j;
            if (node >= n) break;
            float vx = ox[j] + bx;
            float vy = oy[j] + by;
            if (relu) { vx = fmaxf(vx, 0.f); vy = fmaxf(vy, 0.f); }
            if (outc == 64) {
                ((float2*)Hout)[node * 32 + lane] = make_float2(vx, vy);
            } else {
                if (c0 + 1 < outc)
                    *(float2*)(Hout + (size_t)node * outc + c0) = make_float2(vx, vy);
                else if (c0 < outc)
                    Hout[(size_t)node * outc + c0] = vx;
            }
        }
    }
}

// Variants (device globals referenced directly)
__global__ void __launch_bounds__(256, 5)
k_layer0(const float2* __restrict__ x, const float* __restrict__ Wg,
         const float* __restrict__ bg, int n) {
    layer_body(x, g_bufA, Wg, bg, n, 64, 1);
}
__global__ void __launch_bounds__(256, 5)
k_layer_AB(const float* __restrict__ Wg, const float* __restrict__ bg, int n) {
    layer_body((const float2*)g_bufA, g_bufB, Wg, bg, n, 64, 1);
}
__global__ void __launch_bounds__(256, 5)
k_layer_BA(const float* __restrict__ Wg, const float* __restrict__ bg, int n) {
    layer_body((const float2*)g_bufB, g_bufA, Wg, bg, n, 64, 1);
}
__global__ void __launch_bounds__(256, 5)
k_layer_Bout(const float* __restrict__ Wg, const float* __restrict__ bg,
             float* __restrict__ out, int n, int outc) {
    layer_body((const float2*)g_bufB, out, Wg, bg, n, outc, 0);
}

// ---------------------------------------------------------------------------
// Launch
// inputs: x[N,64], edge_weight[E], W[4,64,64], b[4,64], W_out[64,40],
//         b_out[40], edge_src[E], edge_dst[E]  -> out[N,40] f32
// ---------------------------------------------------------------------------
extern "C" void kernel_launch(void* const* d_in, const int* in_sizes, int n_in,
                              void* d_out, int out_size) {
    const float* x    = (const float*)d_in[0];
    const float* ew   = (const float*)d_in[1];
    const float* W    = (const float*)d_in[2];
    const float* b    = (const float*)d_in[3];
    const float* Wout = (const float*)d_in[4];
    const float* bout = (const float*)d_in[5];
    const int*   esrc = (const int*)d_in[6];
    const int*   edst = (const int*)d_in[7];

    int n = in_sizes[0] / 64;   // 100000
    int e = in_sizes[6];        // 1600000

    // --- CSR build (dst-sorted) ---
    k_zero_offs<<<(n + 256) / 256, 256>>>(n + 1);
    k_hist<<<(e + 255) / 256, 256>>>(edst, e);
    k_scan<<<1, 1024>>>(n + 1, n);
    k_scatter<<<(e + 255) / 256, 256>>>(esrc, edst, ew, e);

    // --- 5 fused layers (ping-pong A/B) ---
    k_layer0   <<<LAYER_BLOCKS, 256>>>((const float2*)x, W, b, n);
    k_layer_AB <<<LAYER_BLOCKS, 256>>>(W + 1 * 64 * 64, b + 1 * 64, n);
    k_layer_BA <<<LAYER_BLOCKS, 256>>>(W + 2 * 64 * 64, b + 2 * 64, n);
    k_layer_AB <<<LAYER_BLOCKS, 256>>>(W + 3 * 64 * 64, b + 3 * 64, n);
    k_layer_Bout<<<LAYER_BLOCKS, 256>>>(Wout, bout, (float*)d_out, n, 40);
}